// round 3
// baseline (speedup 1.0000x reference)
#include <cuda_runtime.h>
#include <cuda_bf16.h>
#include <cstddef>

#define NNODES 100000
#define NEDGES 500000
#define FEAT   128

// ---------------- scratch (device globals; no allocations allowed) ----------
__device__ int   g_cnt[NNODES];
__device__ int   g_rowoff[NNODES + 1];
__device__ int   g_cursor[NNODES];
__device__ float g_dinv[NNODES];
__device__ int   g_esrc[NEDGES];
__device__ float g_bufA[(size_t)NNODES * FEAT];
__device__ float g_bufB[(size_t)NNODES * FEAT];
__device__ float g_bufY[(size_t)NNODES * FEAT];
__device__ int   g_bsum[128];
__device__ int   g_boff[128];

// ---------------- CSR build --------------------------------------------------
__global__ void k_init_cnt() {
    int i = blockIdx.x * blockDim.x + threadIdx.x;
    if (i < NNODES) g_cnt[i] = 0;
}

__global__ void k_count(const int* __restrict__ dst) {
    int e = blockIdx.x * blockDim.x + threadIdx.x;
    if (e < NEDGES) atomicAdd(&g_cnt[dst[e]], 1);
}

// block scans 1024 counts (256 thr x 4), writes exclusive partials + block sum
__global__ void k_scan1() {
    __shared__ int sh[256];
    int t = threadIdx.x;
    int base = blockIdx.x * 1024;
    int v[4];
    int s = 0;
#pragma unroll
    for (int j = 0; j < 4; j++) {
        int idx = base + t * 4 + j;
        v[j] = (idx < NNODES) ? g_cnt[idx] : 0;
        s += v[j];
    }
    sh[t] = s;
    __syncthreads();
    for (int off = 1; off < 256; off <<= 1) {
        int x = (t >= off) ? sh[t - off] : 0;
        __syncthreads();
        sh[t] += x;
        __syncthreads();
    }
    int excl = sh[t] - s;
    if (t == 255) g_bsum[blockIdx.x] = sh[255];
    int run = excl;
#pragma unroll
    for (int j = 0; j < 4; j++) {
        int idx = base + t * 4 + j;
        if (idx < NNODES) g_rowoff[idx] = run;
        run += v[j];
    }
}

__global__ void k_scan2(int nb) {
    __shared__ int sh[128];
    int t = threadIdx.x;
    int v = (t < nb) ? g_bsum[t] : 0;
    sh[t] = v;
    __syncthreads();
    for (int off = 1; off < 128; off <<= 1) {
        int x = (t >= off) ? sh[t - off] : 0;
        __syncthreads();
        sh[t] += x;
        __syncthreads();
    }
    g_boff[t] = sh[t] - v;
}

__global__ void k_finalize() {
    int i = blockIdx.x * blockDim.x + threadIdx.x;
    if (i < NNODES) {
        int r = g_rowoff[i] + g_boff[i >> 10];
        g_rowoff[i] = r;
        g_cursor[i] = r;
        g_dinv[i] = rsqrtf((float)(g_cnt[i] + 1));
    }
    if (i == 0) g_rowoff[NNODES] = NEDGES;
}

__global__ void k_fill(const int* __restrict__ src, const int* __restrict__ dst) {
    int e = blockIdx.x * blockDim.x + threadIdx.x;
    if (e < NEDGES) {
        int p = atomicAdd(&g_cursor[dst[e]], 1);
        g_esrc[p] = src[e];
    }
}

// ---------------- GEMM:  Y[i][c] = dinv[i] * sum_k X[i][k] * W[k][c] --------
// X: [N,128], W: [128,Mout], Y: [N,Mout].  128x128 tile, 256 thr, 8x8 blocking.
__global__ __launch_bounds__(256) void k_gemm(const float* __restrict__ X,
                                              const float* __restrict__ W,
                                              float* __restrict__ Y, int Mout) {
    extern __shared__ float smem[];
    float* Xs = smem;               // 128 x 129
    float* Ws = smem + 128 * 129;   // 128 x 128

    int t = threadIdx.x;
    int row0 = blockIdx.x * 128;

    // load W (zero-padded to 128 cols)
    for (int idx = t; idx < 128 * 128; idx += 256) {
        int k = idx >> 7, c = idx & 127;
        Ws[idx] = (c < Mout) ? W[k * Mout + c] : 0.f;
    }
    // load X tile (float4), zero-fill OOB rows
    for (int idx = t; idx < 128 * 32; idx += 256) {
        int r = idx >> 5, kc = (idx & 31) * 4;
        int grow = row0 + r;
        float4 v = (grow < NNODES)
                       ? *(const float4*)(X + (size_t)grow * 128 + kc)
                       : make_float4(0.f, 0.f, 0.f, 0.f);
        float* p = &Xs[r * 129 + kc];
        p[0] = v.x; p[1] = v.y; p[2] = v.z; p[3] = v.w;
    }
    __syncthreads();

    int tx = t & 15, ty = t >> 4;
    int r0 = ty * 8, c0 = tx * 8;
    float acc[8][8];
#pragma unroll
    for (int i = 0; i < 8; i++)
#pragma unroll
        for (int j = 0; j < 8; j++) acc[i][j] = 0.f;

#pragma unroll 8
    for (int k = 0; k < 128; k++) {
        float a[8];
#pragma unroll
        for (int i = 0; i < 8; i++) a[i] = Xs[(r0 + i) * 129 + k];
        float4 b0 = *(const float4*)&Ws[k * 128 + c0];
        float4 b1 = *(const float4*)&Ws[k * 128 + c0 + 4];
        float b[8] = {b0.x, b0.y, b0.z, b0.w, b1.x, b1.y, b1.z, b1.w};
#pragma unroll
        for (int i = 0; i < 8; i++)
#pragma unroll
            for (int j = 0; j < 8; j++) acc[i][j] = fmaf(a[i], b[j], acc[i][j]);
    }

#pragma unroll
    for (int i = 0; i < 8; i++) {
        int gr = row0 + r0 + i;
        if (gr >= NNODES) continue;
        float dv = g_dinv[gr];
        if (Mout == 128) {
            float4 o0 = make_float4(dv * acc[i][0], dv * acc[i][1],
                                    dv * acc[i][2], dv * acc[i][3]);
            float4 o1 = make_float4(dv * acc[i][4], dv * acc[i][5],
                                    dv * acc[i][6], dv * acc[i][7]);
            *(float4*)(Y + (size_t)gr * 128 + c0) = o0;
            *(float4*)(Y + (size_t)gr * 128 + c0 + 4) = o1;
        } else {
#pragma unroll
            for (int j = 0; j < 8; j++) {
                int c = c0 + j;
                if (c < Mout) Y[(size_t)gr * Mout + c] = dv * acc[i][j];
            }
        }
    }
}

// ---------------- aggregation: warp per node ---------------------------------
// out[i] = relu?( dinv[i] * (Ys[i] + sum_{j in-edges} Ys[esrc[j]]) + bias )
__global__ void k_agg(const float* __restrict__ Y, const float* __restrict__ bias,
                      float* __restrict__ Hout, int Mout, int dorelu) {
    int warp = (blockIdx.x * blockDim.x + threadIdx.x) >> 5;
    int lane = threadIdx.x & 31;
    if (warp >= NNODES) return;
    int f = lane * 4;
    if (f >= Mout) return;

    int beg = g_rowoff[warp];
    int end = g_rowoff[warp + 1];

    float4 s = *(const float4*)(Y + (size_t)warp * Mout + f);  // self loop
    for (int j = beg; j < end; j++) {
        int sidx = __ldg(&g_esrc[j]);
        float4 v = __ldg((const float4*)(Y + (size_t)sidx * Mout + f));
        s.x += v.x; s.y += v.y; s.z += v.z; s.w += v.w;
    }
    float dv = g_dinv[warp];
    float4 bb = *(const float4*)(bias + f);
    float4 o = make_float4(fmaf(dv, s.x, bb.x), fmaf(dv, s.y, bb.y),
                           fmaf(dv, s.z, bb.z), fmaf(dv, s.w, bb.w));
    if (dorelu) {
        o.x = fmaxf(o.x, 0.f); o.y = fmaxf(o.y, 0.f);
        o.z = fmaxf(o.z, 0.f); o.w = fmaxf(o.w, 0.f);
    }
    *(float4*)(Hout + (size_t)warp * Mout + f) = o;
}

// ---------------- launch -----------------------------------------------------
extern "C" void kernel_launch(void* const* d_in, const int* in_sizes, int n_in,
                              void* d_out, int out_size) {
    const float* x = (const float*)d_in[0];
    const int* ei = (const int*)d_in[1];
    const int* src = ei;
    const int* dst = ei + NEDGES;
    const float* W0 = (const float*)d_in[2];
    const float* b0 = (const float*)d_in[3];
    const float* W1 = (const float*)d_in[4];
    const float* b1 = (const float*)d_in[5];
    const float* W2 = (const float*)d_in[6];
    const float* b2 = (const float*)d_in[7];
    const float* W3 = (const float*)d_in[8];
    const float* b3 = (const float*)d_in[9];
    float* out = (float*)d_out;

    float *bufA, *bufB, *bufY;
    cudaGetSymbolAddress((void**)&bufA, g_bufA);
    cudaGetSymbolAddress((void**)&bufB, g_bufB);
    cudaGetSymbolAddress((void**)&bufY, g_bufY);

    const int NT = 256;
    int gN = (NNODES + NT - 1) / NT;   // 391
    int gE = (NEDGES + NT - 1) / NT;   // 1954
    int gScan = (NNODES + 1023) / 1024; // 98

    // CSR + norm build
    k_init_cnt<<<gN, NT>>>();
    k_count<<<gE, NT>>>(dst);
    k_scan1<<<gScan, NT>>>();
    k_scan2<<<1, 128>>>(gScan);
    k_finalize<<<gN, NT>>>();
    k_fill<<<gE, NT>>>(src, dst);

    size_t shmem = (128 * 129 + 128 * 128) * sizeof(float);  // 131584
    static int smem_set = 0;
    if (!smem_set) {
        cudaFuncSetAttribute(k_gemm, cudaFuncAttributeMaxDynamicSharedMemorySize,
                             (int)shmem);
        smem_set = 1;
    }

    int gGemm = (NNODES + 127) / 128;          // 782
    int gAgg = (NNODES * 32 + NT - 1) / NT;    // 12500

    // layer 0: x -> bufA
    k_gemm<<<gGemm, NT, shmem>>>(x, W0, bufY, 128);
    k_agg<<<gAgg, NT>>>(bufY, b0, bufA, 128, 1);
    // layer 1: bufA -> bufB
    k_gemm<<<gGemm, NT, shmem>>>(bufA, W1, bufY, 128);
    k_agg<<<gAgg, NT>>>(bufY, b1, bufB, 128, 1);
    // layer 2: bufB -> bufA
    k_gemm<<<gGemm, NT, shmem>>>(bufB, W2, bufY, 128);
    k_agg<<<gAgg, NT>>>(bufY, b2, bufA, 128, 1);
    // layer 3: bufA -> out (C=40, no relu)
    k_gemm<<<gGemm, NT, shmem>>>(bufA, W3, bufY, 40);
    k_agg<<<gAgg, NT>>>(bufY, b3, out, 40, 0);
}

// round 5
// speedup vs baseline: 1.3405x; 1.3405x over previous
#include <cuda_runtime.h>
#include <cuda_bf16.h>
#include <cstdint>
#include <cstddef>

#define NNODES 100000
#define NEDGES 500000
#define FEAT   128

// ---------------- scratch (device globals; no allocations allowed) ----------
__device__ int   g_cnt[NNODES];
__device__ int   g_rowoff[NNODES + 1];
__device__ int   g_cursor[NNODES];
__device__ float g_dinv[NNODES];
__device__ int   g_esrc[NEDGES];
__device__ float g_bufA[(size_t)NNODES * FEAT];
__device__ float g_bufB[(size_t)NNODES * FEAT];
__device__ float g_bufY[(size_t)NNODES * FEAT];
__device__ int   g_bsum[128];
__device__ int   g_boff[128];

// ---------------- CSR build --------------------------------------------------
__global__ void k_init_cnt() {
    int i = blockIdx.x * blockDim.x + threadIdx.x;
    if (i < NNODES) g_cnt[i] = 0;
}

__global__ void k_count(const int* __restrict__ dst) {
    int e = blockIdx.x * blockDim.x + threadIdx.x;
    if (e < NEDGES) atomicAdd(&g_cnt[dst[e]], 1);
}

__global__ void k_scan1() {
    __shared__ int sh[256];
    int t = threadIdx.x;
    int base = blockIdx.x * 1024;
    int v[4];
    int s = 0;
#pragma unroll
    for (int j = 0; j < 4; j++) {
        int idx = base + t * 4 + j;
        v[j] = (idx < NNODES) ? g_cnt[idx] : 0;
        s += v[j];
    }
    sh[t] = s;
    __syncthreads();
    for (int off = 1; off < 256; off <<= 1) {
        int x = (t >= off) ? sh[t - off] : 0;
        __syncthreads();
        sh[t] += x;
        __syncthreads();
    }
    int excl = sh[t] - s;
    if (t == 255) g_bsum[blockIdx.x] = sh[255];
    int run = excl;
#pragma unroll
    for (int j = 0; j < 4; j++) {
        int idx = base + t * 4 + j;
        if (idx < NNODES) g_rowoff[idx] = run;
        run += v[j];
    }
}

__global__ void k_scan2(int nb) {
    __shared__ int sh[128];
    int t = threadIdx.x;
    int v = (t < nb) ? g_bsum[t] : 0;
    sh[t] = v;
    __syncthreads();
    for (int off = 1; off < 128; off <<= 1) {
        int x = (t >= off) ? sh[t - off] : 0;
        __syncthreads();
        sh[t] += x;
        __syncthreads();
    }
    g_boff[t] = sh[t] - v;
}

__global__ void k_finalize() {
    int i = blockIdx.x * blockDim.x + threadIdx.x;
    if (i < NNODES) {
        int r = g_rowoff[i] + g_boff[i >> 10];
        g_rowoff[i] = r;
        g_cursor[i] = r;
        g_dinv[i] = rsqrtf((float)(g_cnt[i] + 1));
    }
    if (i == 0) g_rowoff[NNODES] = NEDGES;
}

__global__ void k_fill(const int* __restrict__ src, const int* __restrict__ dst) {
    int e = blockIdx.x * blockDim.x + threadIdx.x;
    if (e < NEDGES) {
        int p = atomicAdd(&g_cursor[dst[e]], 1);
        g_esrc[p] = src[e];
    }
}

// ---------------- tensor-core GEMM ------------------------------------------
// Y[i][c] = dinv[i] * sum_k X[i][k] * W[k][c]
// 128x128 CTA tile, 256 thr = 8 warps (4 x 2), warp tile 32x64.
// mma.sync.m16n8k8 tf32.  SMEM holds fragments in register-layout order so
// each A-frag is one ld.shared.v4 and each B-frag one ld.shared.v2.
__device__ __forceinline__ uint32_t f2tf32(float v) {
    uint32_t r;
    asm("cvt.rna.tf32.f32 %0, %1;" : "=r"(r) : "f"(v));
    return r;
}

__global__ __launch_bounds__(256) void k_gemm_tc(const float* __restrict__ X,
                                                const float* __restrict__ W,
                                                float* __restrict__ Y, int Mout) {
    extern __shared__ float smem[];
    float* As = smem;           // [8 mtile][16 kstep][32 lane][4]  = 16384 floats
    float* Bs = smem + 16384;   // [16 ntile][16 kstep][32 lane][2] = 16384 floats

    int t = threadIdx.x;
    int row0 = blockIdx.x * 128;

    // W -> Bs (permuted, tf32, zero-pad cols >= Mout)
    for (int idx = t; idx < 128 * 128; idx += 256) {
        int k = idx >> 7, c = idx & 127;
        float v = (c < Mout) ? W[k * Mout + c] : 0.f;
        int ntile = c >> 3, gid = c & 7;
        int kstep = k >> 3, klow = k & 7, slot = klow >> 2, tig = klow & 3;
        Bs[((ntile * 16 + kstep) * 32 + gid * 4 + tig) * 2 + slot] =
            __uint_as_float(f2tf32(v));
    }
    // X tile -> As (permuted, tf32, zero-fill OOB rows)
    for (int idx = t; idx < 128 * 32; idx += 256) {
        int r = idx >> 5;
        int kc = (idx & 31) * 4;
        int grow = row0 + r;
        float4 v = (grow < NNODES)
                       ? *(const float4*)(X + (size_t)grow * 128 + kc)
                       : make_float4(0.f, 0.f, 0.f, 0.f);
        float vv[4] = {v.x, v.y, v.z, v.w};
        int mtile = r >> 4, rlow = r & 15;
        int half = rlow >> 3, gid = rlow & 7;
#pragma unroll
        for (int j = 0; j < 4; j++) {
            int k = kc + j;
            int kstep = k >> 3, klow = k & 7, khalf = klow >> 2, tig = klow & 3;
            As[((mtile * 16 + kstep) * 32 + gid * 4 + tig) * 4 + half + 2 * khalf] =
                __uint_as_float(f2tf32(vv[j]));
        }
    }
    __syncthreads();

    int warp = t >> 5, lane = t & 31;
    int wm = warp >> 1, wn = warp & 1;  // 4 x 2 warp grid

    float acc[2][8][4];
#pragma unroll
    for (int im = 0; im < 2; im++)
#pragma unroll
        for (int in = 0; in < 8; in++)
#pragma unroll
            for (int j = 0; j < 4; j++) acc[im][in][j] = 0.f;

#pragma unroll 4
    for (int ks = 0; ks < 16; ks++) {
        uint4 a[2];
#pragma unroll
        for (int im = 0; im < 2; im++)
            a[im] = *(const uint4*)&As[(((wm * 2 + im) * 16 + ks) * 32 + lane) * 4];
        uint2 b[8];
#pragma unroll
        for (int in = 0; in < 8; in++)
            b[in] = *(const uint2*)&Bs[(((wn * 8 + in) * 16 + ks) * 32 + lane) * 2];
#pragma unroll
        for (int im = 0; im < 2; im++)
#pragma unroll
            for (int in = 0; in < 8; in++)
                asm volatile(
                    "mma.sync.aligned.m16n8k8.row.col.f32.tf32.tf32.f32 "
                    "{%0,%1,%2,%3}, {%4,%5,%6,%7}, {%8,%9}, {%0,%1,%2,%3};"
                    : "+f"(acc[im][in][0]), "+f"(acc[im][in][1]),
                      "+f"(acc[im][in][2]), "+f"(acc[im][in][3])
                    : "r"(a[im].x), "r"(a[im].y), "r"(a[im].z), "r"(a[im].w),
                      "r"(b[in].x), "r"(b[in].y));
    }

    // epilogue: c0:(gid, tig*2) c1:(gid, tig*2+1) c2:(gid+8, ...) c3
    int gid = lane >> 2, tig = lane & 3;
#pragma unroll
    for (int im = 0; im < 2; im++) {
        int r_lo = row0 + wm * 32 + im * 16 + gid;
        int r_hi = r_lo + 8;
        float dv0 = (r_lo < NNODES) ? g_dinv[r_lo] : 0.f;
        float dv1 = (r_hi < NNODES) ? g_dinv[r_hi] : 0.f;
#pragma unroll
        for (int in = 0; in < 8; in++) {
            int c = wn * 64 + in * 8 + tig * 2;
            if (Mout == 128) {
                if (r_lo < NNODES) {
                    float2 o = make_float2(dv0 * acc[im][in][0], dv0 * acc[im][in][1]);
                    *(float2*)(Y + (size_t)r_lo * 128 + c) = o;
                }
                if (r_hi < NNODES) {
                    float2 o = make_float2(dv1 * acc[im][in][2], dv1 * acc[im][in][3]);
                    *(float2*)(Y + (size_t)r_hi * 128 + c) = o;
                }
            } else {
                if (r_lo < NNODES) {
                    if (c < Mout)     Y[(size_t)r_lo * Mout + c]     = dv0 * acc[im][in][0];
                    if (c + 1 < Mout) Y[(size_t)r_lo * Mout + c + 1] = dv0 * acc[im][in][1];
                }
                if (r_hi < NNODES) {
                    if (c < Mout)     Y[(size_t)r_hi * Mout + c]     = dv1 * acc[im][in][2];
                    if (c + 1 < Mout) Y[(size_t)r_hi * Mout + c + 1] = dv1 * acc[im][in][3];
                }
            }
        }
    }
}

// ---------------- aggregation: warp per node ---------------------------------
// out[i] = relu?( dinv[i] * (Ys[i] + sum_{j in-edges} Ys[esrc[j]]) + bias )
__global__ void k_agg(const float* __restrict__ Y, const float* __restrict__ bias,
                      float* __restrict__ Hout, int Mout, int dorelu) {
    int warp = (blockIdx.x * blockDim.x + threadIdx.x) >> 5;
    int lane = threadIdx.x & 31;
    if (warp >= NNODES) return;
    int f = lane * 4;
    if (f >= Mout) return;

    int beg = g_rowoff[warp];
    int end = g_rowoff[warp + 1];

    float4 s = *(const float4*)(Y + (size_t)warp * Mout + f);  // self loop
    for (int j = beg; j < end; j++) {
        int sidx = __ldg(&g_esrc[j]);
        float4 v = __ldg((const float4*)(Y + (size_t)sidx * Mout + f));
        s.x += v.x; s.y += v.y; s.z += v.z; s.w += v.w;
    }
    float dv = g_dinv[warp];
    float4 bb = *(const float4*)(bias + f);
    float4 o = make_float4(fmaf(dv, s.x, bb.x), fmaf(dv, s.y, bb.y),
                           fmaf(dv, s.z, bb.z), fmaf(dv, s.w, bb.w));
    if (dorelu) {
        o.x = fmaxf(o.x, 0.f); o.y = fmaxf(o.y, 0.f);
        o.z = fmaxf(o.z, 0.f); o.w = fmaxf(o.w, 0.f);
    }
    *(float4*)(Hout + (size_t)warp * Mout + f) = o;
}

// ---------------- launch -----------------------------------------------------
extern "C" void kernel_launch(void* const* d_in, const int* in_sizes, int n_in,
                              void* d_out, int out_size) {
    const float* x = (const float*)d_in[0];
    const int* ei = (const int*)d_in[1];
    const int* src = ei;
    const int* dst = ei + NEDGES;
    const float* W0 = (const float*)d_in[2];
    const float* b0 = (const float*)d_in[3];
    const float* W1 = (const float*)d_in[4];
    const float* b1 = (const float*)d_in[5];
    const float* W2 = (const float*)d_in[6];
    const float* b2 = (const float*)d_in[7];
    const float* W3 = (const float*)d_in[8];
    const float* b3 = (const float*)d_in[9];
    float* out = (float*)d_out;

    float *bufA, *bufB, *bufY;
    cudaGetSymbolAddress((void**)&bufA, g_bufA);
    cudaGetSymbolAddress((void**)&bufB, g_bufB);
    cudaGetSymbolAddress((void**)&bufY, g_bufY);

    const int NT = 256;
    int gN = (NNODES + NT - 1) / NT;
    int gE = (NEDGES + NT - 1) / NT;
    int gScan = (NNODES + 1023) / 1024;

    // CSR + norm build
    k_init_cnt<<<gN, NT>>>();
    k_count<<<gE, NT>>>(dst);
    k_scan1<<<gScan, NT>>>();
    k_scan2<<<1, 128>>>(gScan);
    k_finalize<<<gN, NT>>>();
    k_fill<<<gE, NT>>>(src, dst);

    size_t shmem = 2 * 16384 * sizeof(float);  // 131072 B
    static int smem_set = 0;
    if (!smem_set) {
        cudaFuncSetAttribute(k_gemm_tc, cudaFuncAttributeMaxDynamicSharedMemorySize,
                             (int)shmem);
        smem_set = 1;
    }

    int gGemm = (NNODES + 127) / 128;          // 782
    int gAgg = (NNODES * 32 + NT - 1) / NT;    // 12500

    // layer 0
    k_gemm_tc<<<gGemm, NT, shmem>>>(x, W0, bufY, 128);
    k_agg<<<gAgg, NT>>>(bufY, b0, bufA, 128, 1);
    // layer 1
    k_gemm_tc<<<gGemm, NT, shmem>>>(bufA, W1, bufY, 128);
    k_agg<<<gAgg, NT>>>(bufY, b1, bufB, 128, 1);
    // layer 2
    k_gemm_tc<<<gGemm, NT, shmem>>>(bufB, W2, bufY, 128);
    k_agg<<<gAgg, NT>>>(bufY, b2, bufA, 128, 1);
    // layer 3 (C = 40, no relu)
    k_gemm_tc<<<gGemm, NT, shmem>>>(bufA, W3, bufY, 40);
    k_agg<<<gAgg, NT>>>(bufY, b3, out, 40, 0);
}

// round 7
// speedup vs baseline: 1.9366x; 1.4447x over previous
#include <cuda_runtime.h>
#include <cuda_bf16.h>
#include <cstdint>
#include <cstddef>

#define NNODES 100000
#define NEDGES 500000
#define FEAT   128

// ---------------- scratch (device globals; no allocations allowed) ----------
__device__ int      g_cnt[NNODES];
__device__ int      g_rowoff[NNODES + 1];
__device__ int      g_cursor[NNODES];
__device__ float    g_dinv[NNODES];
__device__ int      g_esrc[NEDGES];
__device__ float    g_bufA[(size_t)NNODES * FEAT];
__device__ float    g_bufB[(size_t)NNODES * FEAT];
__device__ float    g_bufY[(size_t)NNODES * FEAT];
__device__ uint32_t g_Wp[16 * 16 * 32 * 2];   // permuted tf32 W fragments, 64KB
__device__ int      g_bsum[128];
__device__ int      g_boff[128];

// ---------------- CSR build --------------------------------------------------
__global__ void k_init_cnt() {
    int i = blockIdx.x * blockDim.x + threadIdx.x;
    if (i < NNODES) g_cnt[i] = 0;
}

__global__ void k_count(const int* __restrict__ dst) {
    int e = blockIdx.x * blockDim.x + threadIdx.x;
    if (e < NEDGES) atomicAdd(&g_cnt[dst[e]], 1);
}

__global__ void k_scan1() {
    __shared__ int sh[256];
    int t = threadIdx.x;
    int base = blockIdx.x * 1024;
    int v[4];
    int s = 0;
#pragma unroll
    for (int j = 0; j < 4; j++) {
        int idx = base + t * 4 + j;
        v[j] = (idx < NNODES) ? g_cnt[idx] : 0;
        s += v[j];
    }
    sh[t] = s;
    __syncthreads();
    for (int off = 1; off < 256; off <<= 1) {
        int x = (t >= off) ? sh[t - off] : 0;
        __syncthreads();
        sh[t] += x;
        __syncthreads();
    }
    int excl = sh[t] - s;
    if (t == 255) g_bsum[blockIdx.x] = sh[255];
    int run = excl;
#pragma unroll
    for (int j = 0; j < 4; j++) {
        int idx = base + t * 4 + j;
        if (idx < NNODES) g_rowoff[idx] = run;
        run += v[j];
    }
}

__global__ void k_scan2(int nb) {
    __shared__ int sh[128];
    int t = threadIdx.x;
    int v = (t < nb) ? g_bsum[t] : 0;
    sh[t] = v;
    __syncthreads();
    for (int off = 1; off < 128; off <<= 1) {
        int x = (t >= off) ? sh[t - off] : 0;
        __syncthreads();
        sh[t] += x;
        __syncthreads();
    }
    g_boff[t] = sh[t] - v;
}

__global__ void k_finalize() {
    int i = blockIdx.x * blockDim.x + threadIdx.x;
    if (i < NNODES) {
        int r = g_rowoff[i] + g_boff[i >> 10];
        g_rowoff[i] = r;
        g_cursor[i] = r;
        g_dinv[i] = rsqrtf((float)(g_cnt[i] + 1));
    }
    if (i == 0) g_rowoff[NNODES] = NEDGES;
}

__global__ void k_fill(const int* __restrict__ src, const int* __restrict__ dst) {
    int e = blockIdx.x * blockDim.x + threadIdx.x;
    if (e < NEDGES) {
        int p = atomicAdd(&g_cursor[dst[e]], 1);
        g_esrc[p] = src[e];
    }
}

// ---------------- W permute (once per layer, 16K elems) ----------------------
__device__ __forceinline__ uint32_t f2tf32(float v) {
    uint32_t r;
    asm("cvt.rna.tf32.f32 %0, %1;" : "=r"(r) : "f"(v));
    return r;
}

__global__ void k_prepW(const float* __restrict__ W, int Mout) {
    int idx = blockIdx.x * blockDim.x + threadIdx.x;  // 0..16383
    int k = idx >> 7, c = idx & 127;
    float v = (c < Mout) ? W[k * Mout + c] : 0.f;
    int ntile = c >> 3, gid = c & 7;
    int kstep = k >> 3, klow = k & 7, slot = klow >> 2, tig = klow & 3;
    g_Wp[((ntile * 16 + kstep) * 32 + gid * 4 + tig) * 2 + slot] = f2tf32(v);
}

// ---------------- tensor-core GEMM ------------------------------------------
// Y[i][c] = dinv[i] * sum_k X[i][k] * W[k][c]
// 128x128 CTA tile, 256 thr = 8 warps (4x2), warp tile 32x64.
// A fragments staged in SMEM (permuted); B fragments read from g_Wp (L1-hot).
__global__ __launch_bounds__(256, 2) void k_gemm_tc(const float* __restrict__ X,
                                                    float* __restrict__ Y, int Mout) {
    extern __shared__ float smem[];
    float* As = smem;  // [8 mtile][16 kstep][32 lane][4] = 16384 floats = 64KB

    int t = threadIdx.x;
    int row0 = blockIdx.x * 128;

    // X tile -> As (permuted, tf32, zero-fill OOB rows)
    for (int idx = t; idx < 128 * 32; idx += 256) {
        int r = idx >> 5;
        int kc = (idx & 31) * 4;
        int grow = row0 + r;
        float4 v = (grow < NNODES)
                       ? *(const float4*)(X + (size_t)grow * 128 + kc)
                       : make_float4(0.f, 0.f, 0.f, 0.f);
        float vv[4] = {v.x, v.y, v.z, v.w};
        int mtile = r >> 4, rlow = r & 15;
        int half = rlow >> 3, gid = rlow & 7;
#pragma unroll
        for (int j = 0; j < 4; j++) {
            int k = kc + j;
            int kstep = k >> 3, klow = k & 7, khalf = klow >> 2, tig = klow & 3;
            As[((mtile * 16 + kstep) * 32 + gid * 4 + tig) * 4 + half + 2 * khalf] =
                __uint_as_float(f2tf32(vv[j]));
        }
    }
    __syncthreads();

    int warp = t >> 5, lane = t & 31;
    int wm = warp >> 1, wn = warp & 1;  // 4 x 2 warp grid

    float acc[2][8][4];
#pragma unroll
    for (int im = 0; im < 2; im++)
#pragma unroll
        for (int in = 0; in < 8; in++)
#pragma unroll
            for (int j = 0; j < 4; j++) acc[im][in][j] = 0.f;

#pragma unroll 4
    for (int ks = 0; ks < 16; ks++) {
        uint4 a[2];
#pragma unroll
        for (int im = 0; im < 2; im++)
            a[im] = *(const uint4*)&As[(((wm * 2 + im) * 16 + ks) * 32 + lane) * 4];
        uint2 b[8];
#pragma unroll
        for (int in = 0; in < 8; in++)
            b[in] = __ldg((const uint2*)&g_Wp[(((wn * 8 + in) * 16 + ks) * 32 + lane) * 2]);
#pragma unroll
        for (int im = 0; im < 2; im++)
#pragma unroll
            for (int in = 0; in < 8; in++)
                asm volatile(
                    "mma.sync.aligned.m16n8k8.row.col.f32.tf32.tf32.f32 "
                    "{%0,%1,%2,%3}, {%4,%5,%6,%7}, {%8,%9}, {%0,%1,%2,%3};"
                    : "+f"(acc[im][in][0]), "+f"(acc[im][in][1]),
                      "+f"(acc[im][in][2]), "+f"(acc[im][in][3])
                    : "r"(a[im].x), "r"(a[im].y), "r"(a[im].z), "r"(a[im].w),
                      "r"(b[in].x), "r"(b[in].y));
    }

    // epilogue: c0:(gid, tig*2) c1:(gid, tig*2+1) c2:(gid+8, ...) c3
    int gid = lane >> 2, tig = lane & 3;
#pragma unroll
    for (int im = 0; im < 2; im++) {
        int r_lo = row0 + wm * 32 + im * 16 + gid;
        int r_hi = r_lo + 8;
        float dv0 = (r_lo < NNODES) ? g_dinv[r_lo] : 0.f;
        float dv1 = (r_hi < NNODES) ? g_dinv[r_hi] : 0.f;
#pragma unroll
        for (int in = 0; in < 8; in++) {
            int c = wn * 64 + in * 8 + tig * 2;
            if (Mout == 128) {
                if (r_lo < NNODES) {
                    float2 o = make_float2(dv0 * acc[im][in][0], dv0 * acc[im][in][1]);
                    *(float2*)(Y + (size_t)r_lo * 128 + c) = o;
                }
                if (r_hi < NNODES) {
                    float2 o = make_float2(dv1 * acc[im][in][2], dv1 * acc[im][in][3]);
                    *(float2*)(Y + (size_t)r_hi * 128 + c) = o;
                }
            } else {
                if (r_lo < NNODES) {
                    if (c < Mout)     Y[(size_t)r_lo * Mout + c]     = dv0 * acc[im][in][0];
                    if (c + 1 < Mout) Y[(size_t)r_lo * Mout + c + 1] = dv0 * acc[im][in][1];
                }
                if (r_hi < NNODES) {
                    if (c < Mout)     Y[(size_t)r_hi * Mout + c]     = dv1 * acc[im][in][2];
                    if (c + 1 < Mout) Y[(size_t)r_hi * Mout + c + 1] = dv1 * acc[im][in][3];
                }
            }
        }
    }
}

// ---------------- aggregation: warp per node, 4-way pipelined gather ---------
// out[i] = relu?( dinv[i] * (Ys[i] + sum_{j in-edges} Ys[esrc[j]]) + bias )
__global__ void k_agg(const float* __restrict__ Y, const float* __restrict__ bias,
                      float* __restrict__ Hout, int Mout, int dorelu) {
    int warp = (blockIdx.x * blockDim.x + threadIdx.x) >> 5;
    int lane = threadIdx.x & 31;
    if (warp >= NNODES) return;
    int f = lane * 4;
    if (f >= Mout) return;

    int beg = g_rowoff[warp];
    int end = g_rowoff[warp + 1];

    float4 s0 = *(const float4*)(Y + (size_t)warp * Mout + f);  // self loop
    float4 s1 = make_float4(0.f, 0.f, 0.f, 0.f);

    int j = beg;
    for (; j + 4 <= end; j += 4) {
        int i0 = __ldg(&g_esrc[j]);
        int i1 = __ldg(&g_esrc[j + 1]);
        int i2 = __ldg(&g_esrc[j + 2]);
        int i3 = __ldg(&g_esrc[j + 3]);
        float4 v0 = __ldg((const float4*)(Y + (size_t)i0 * Mout + f));
        float4 v1 = __ldg((const float4*)(Y + (size_t)i1 * Mout + f));
        float4 v2 = __ldg((const float4*)(Y + (size_t)i2 * Mout + f));
        float4 v3 = __ldg((const float4*)(Y + (size_t)i3 * Mout + f));
        s0.x += v0.x; s0.y += v0.y; s0.z += v0.z; s0.w += v0.w;
        s1.x += v1.x; s1.y += v1.y; s1.z += v1.z; s1.w += v1.w;
        s0.x += v2.x; s0.y += v2.y; s0.z += v2.z; s0.w += v2.w;
        s1.x += v3.x; s1.y += v3.y; s1.z += v3.z; s1.w += v3.w;
    }
    for (; j < end; j++) {
        int si = __ldg(&g_esrc[j]);
        float4 v = __ldg((const float4*)(Y + (size_t)si * Mout + f));
        s0.x += v.x; s0.y += v.y; s0.z += v.z; s0.w += v.w;
    }
    float4 s = make_float4(s0.x + s1.x, s0.y + s1.y, s0.z + s1.z, s0.w + s1.w);

    float dv = g_dinv[warp];
    float4 bb = *(const float4*)(bias + f);
    float4 o = make_float4(fmaf(dv, s.x, bb.x), fmaf(dv, s.y, bb.y),
                           fmaf(dv, s.z, bb.z), fmaf(dv, s.w, bb.w));
    if (dorelu) {
        o.x = fmaxf(o.x, 0.f); o.y = fmaxf(o.y, 0.f);
        o.z = fmaxf(o.z, 0.f); o.w = fmaxf(o.w, 0.f);
    }
    *(float4*)(Hout + (size_t)warp * Mout + f) = o;
}

// ---------------- launch -----------------------------------------------------
extern "C" void kernel_launch(void* const* d_in, const int* in_sizes, int n_in,
                              void* d_out, int out_size) {
    const float* x = (const float*)d_in[0];
    const int* ei = (const int*)d_in[1];
    const int* src = ei;
    const int* dst = ei + NEDGES;
    const float* W0 = (const float*)d_in[2];
    const float* b0 = (const float*)d_in[3];
    const float* W1 = (const float*)d_in[4];
    const float* b1 = (const float*)d_in[5];
    const float* W2 = (const float*)d_in[6];
    const float* b2 = (const float*)d_in[7];
    const float* W3 = (const float*)d_in[8];
    const float* b3 = (const float*)d_in[9];
    float* out = (float*)d_out;

    float *bufA, *bufB, *bufY;
    cudaGetSymbolAddress((void**)&bufA, g_bufA);
    cudaGetSymbolAddress((void**)&bufB, g_bufB);
    cudaGetSymbolAddress((void**)&bufY, g_bufY);

    const int NT = 256;
    int gN = (NNODES + NT - 1) / NT;
    int gE = (NEDGES + NT - 1) / NT;
    int gScan = (NNODES + 1023) / 1024;

    // CSR + norm build
    k_init_cnt<<<gN, NT>>>();
    k_count<<<gE, NT>>>(dst);
    k_scan1<<<gScan, NT>>>();
    k_scan2<<<1, 128>>>(gScan);
    k_finalize<<<gN, NT>>>();
    k_fill<<<gE, NT>>>(src, dst);

    size_t shmem = 16384 * sizeof(float);  // 64KB (As only)
    static int smem_set = 0;
    if (!smem_set) {
        cudaFuncSetAttribute(k_gemm_tc, cudaFuncAttributeMaxDynamicSharedMemorySize,
                             (int)shmem);
        smem_set = 1;
    }

    int gGemm = (NNODES + 127) / 128;          // 782
    int gAgg = (NNODES * 32 + NT - 1) / NT;    // 12500

    // layer 0
    k_prepW<<<64, 256>>>(W0, 128);
    k_gemm_tc<<<gGemm, NT, shmem>>>(x, bufY, 128);
    k_agg<<<gAgg, NT>>>(bufY, b0, bufA, 128, 1);
    // layer 1
    k_prepW<<<64, 256>>>(W1, 128);
    k_gemm_tc<<<gGemm, NT, shmem>>>(bufA, bufY, 128);
    k_agg<<<gAgg, NT>>>(bufY, b1, bufB, 128, 1);
    // layer 2
    k_prepW<<<64, 256>>>(W2, 128);
    k_gemm_tc<<<gGemm, NT, shmem>>>(bufB, bufY, 128);
    k_agg<<<gAgg, NT>>>(bufY, b2, bufA, 128, 1);
    // layer 3 (C = 40, no relu)
    k_prepW<<<64, 256>>>(W3, 40);
    k_gemm_tc<<<gGemm, NT, shmem>>>(bufA, bufY, 40);
    k_agg<<<gAgg, NT>>>(bufY, b3, out, 40, 0);
}